// round 14
// baseline (speedup 1.0000x reference)
#include <cuda_runtime.h>
#include <cuda_bf16.h>
#include <cuda_fp16.h>
#include <cstdint>

#define N_NODES 100000
#define N_EDGES 1600000
#define N_GRAPHS 64
#define D 128

#define SCAN_T 1024
#define NB ((N_NODES + SCAN_T - 1) / SCAN_T)   // 98

// chunk split for agg1 <-> gemm2 pipeline (tile = 256 rows)
#define TILES_TOTAL 391
#define TILES_C0 196
#define ROWS_C0 (TILES_C0 * 256)   // 50176

// ---------------- scratch (device globals; no allocation allowed) ----------
__device__ uint2  g_x16[(size_t)N_NODES * 32]; // X in fp16 (packed 4/uint2)
__device__ __half g_t1[(size_t)N_NODES * D];  // dinv ⊙ (X@W1), fp16
__device__ __half g_h1[(size_t)N_NODES * D];  // dinv ⊙ relu(...), fp16
__device__ __half g_t2[(size_t)N_NODES * D];  // dinv ⊙ (h1@W2), fp16
__device__ int   g_deg[N_NODES];              // zeroed by k_fused_ap for next call
__device__ float g_dinv[N_NODES];
__device__ int   g_off[N_NODES + 1];
__device__ int   g_cur[N_NODES];
__device__ int   g_csr[N_EDGES];              // src only (weights factored out)
__device__ int   g_bsum[NB];                  // re-armed to -1 by k_deg
__device__ float g_pool[N_GRAPHS * D];        // zeroed by k_gemm
__device__ int   g_cnt[N_GRAPHS];
__device__ int   g_is64;
__device__ uint32_t g_W16[2][D * 64];         // W^T fp16, packed pairs [n][k/2]

// ---------------- helpers ---------------------------------------------------
__device__ __forceinline__ int load_idx(const void* p, long long i) {
    if (g_is64) return (int)((const long long*)p)[i];
    return ((const int*)p)[i];
}

__device__ __forceinline__ int detect64(const void* ep) {
    const int* p = (const int*)ep;
    int is64 = 1;
    #pragma unroll
    for (int j = 0; j < 8; j++)
        if (p[2 * j + 1] != 0) is64 = 0;
    return is64;
}

__device__ __forceinline__ void mma16f(float* c, const uint32_t* a,
                                       const uint32_t* b) {
    asm volatile(
        "mma.sync.aligned.m16n8k16.row.col.f32.f16.f16.f32 "
        "{%0,%1,%2,%3}, {%4,%5,%6,%7}, {%8,%9}, {%0,%1,%2,%3};"
        : "+f"(c[0]), "+f"(c[1]), "+f"(c[2]), "+f"(c[3])
        : "r"(a[0]), "r"(a[1]), "r"(a[2]), "r"(a[3]), "r"(b[0]), "r"(b[1]));
}

__device__ __forceinline__ void ldsm_x4(uint32_t& r0, uint32_t& r1,
                                        uint32_t& r2, uint32_t& r3,
                                        uint32_t addr) {
    asm volatile(
        "ldmatrix.sync.aligned.m8n8.x4.shared.b16 {%0,%1,%2,%3}, [%4];"
        : "=r"(r0), "=r"(r1), "=r"(r2), "=r"(r3) : "r"(addr));
}

__device__ __forceinline__ uint32_t sptr(const void* p) {
    return (uint32_t)__cvta_generic_to_shared(p);
}

__device__ __forceinline__ void cp_async16(uint32_t dst, const void* src,
                                           uint32_t srcsize) {
    asm volatile("cp.async.ca.shared.global [%0], [%1], 16, %2;"
                 :: "r"(dst), "l"(src), "r"(srcsize) : "memory");
}
__device__ __forceinline__ void cp_commit() {
    asm volatile("cp.async.commit_group;" ::: "memory");
}
template <int N>
__device__ __forceinline__ void cp_wait() {
    asm volatile("cp.async.wait_group %0;" :: "n"(N) : "memory");
}

__device__ __forceinline__ float4 h4tof4(uint2 v) {
    float2 a = __half22float2(*reinterpret_cast<__half2*>(&v.x));
    float2 b = __half22float2(*reinterpret_cast<__half2*>(&v.y));
    return make_float4(a.x, a.y, b.x, b.y);
}

__device__ __forceinline__ uint2 f4toh4(float4 v) {
    __half2 a = __float22half2_rn(make_float2(v.x, v.y));
    __half2 b = __float22half2_rn(make_float2(v.z, v.w));
    uint2 o;
    o.x = *reinterpret_cast<uint32_t*>(&a);
    o.y = *reinterpret_cast<uint32_t*>(&b);
    return o;
}

// unweighted gather-sum of pre-scaled fp16 rows (self row included)
__device__ __forceinline__ float4 gather_sum16(const uint2* __restrict__ hp,
                                               int node, int lane) {
    float4 acc[4];
    acc[0] = h4tof4(hp[(size_t)node * 32 + lane]);   // self row (pre-scaled)
    acc[1] = make_float4(0.f, 0.f, 0.f, 0.f);
    acc[2] = acc[1];
    acc[3] = acc[1];

    int e = g_off[node];
    const int end = g_off[node + 1];
    for (; e + 3 < end; e += 4) {
        int s[4];
        #pragma unroll
        for (int j = 0; j < 4; j++) s[j] = g_csr[e + j];
        uint2 raw[4];
        #pragma unroll
        for (int j = 0; j < 4; j++) raw[j] = hp[(size_t)s[j] * 32 + lane];
        #pragma unroll
        for (int j = 0; j < 4; j++) {
            float4 v = h4tof4(raw[j]);
            acc[j].x += v.x; acc[j].y += v.y;
            acc[j].z += v.z; acc[j].w += v.w;
        }
    }
    for (; e < end; e++) {
        float4 v = h4tof4(hp[(size_t)g_csr[e] * 32 + lane]);
        acc[0].x += v.x; acc[0].y += v.y;
        acc[0].z += v.z; acc[0].w += v.w;
    }
    return make_float4(acc[0].x + acc[1].x + acc[2].x + acc[3].x,
                       acc[0].y + acc[1].y + acc[2].y + acc[3].y,
                       acc[0].z + acc[1].z + acc[2].z + acc[3].z,
                       acc[0].w + acc[1].w + acc[2].w + acc[3].w);
}

// ---------------- branch B: convert W + X to fp16 ----------------------------
__global__ void k_conv(const float* X, const float* W1, const float* W2) {
    int i = blockIdx.x * blockDim.x + threadIdx.x;
    if (i < 2 * D * 64) {
        int m = i >> 13;
        int j = i & 8191;
        int n = j >> 6, kp = j & 63;
        const float* W = m ? W2 : W1;
        float a = W[(2 * kp) * D + n];
        float b = W[(2 * kp + 1) * D + n];
        __half2 h = __float22half2_rn(make_float2(a, b));
        g_W16[m][n * 64 + kp] = *reinterpret_cast<uint32_t*>(&h);
    }
    #pragma unroll
    for (int j = 0; j < 2; j++) {
        int idx = i + j * (N_NODES * 16);
        if (idx < N_NODES * 32)
            g_x16[idx] = f4toh4(((const float4*)X)[idx]);
    }
}

// ---------------- branch A: deg count + dtype + sentinels --------------------
__global__ void k_deg(const void* ep) {
    int i = blockIdx.x * blockDim.x + threadIdx.x;
    if (i == 0) {
        g_is64 = detect64(ep);
        g_off[N_NODES] = N_EDGES;
    }
    if (i < NB) g_bsum[i] = -1;
    if (i < N_EDGES) {
        int is64 = detect64(ep);
        int d = is64 ? (int)((const long long*)ep)[(long long)N_EDGES + i]
                     : ((const int*)ep)[N_EDGES + i];
        atomicAdd(&g_deg[d], 1);
    }
}

// ---------------- single-pass scan (98 blocks = 1 wave; spin publication) ---
__global__ void k_scan() {
    __shared__ int s[SCAN_T];
    __shared__ int s_boff;
    const int b = blockIdx.x;
    const int t = threadIdx.x;
    const int i = b * SCAN_T + t;
    int v = (i < N_NODES) ? g_deg[i] : 0;
    if (i < N_NODES) g_dinv[i] = rsqrtf((float)v + 1.0f);  // +1 self loop
    s[t] = v;
    if (t == 0) s_boff = 0;
    __syncthreads();
    #pragma unroll
    for (int off = 1; off < SCAN_T; off <<= 1) {
        int u = (t >= off) ? s[t - off] : 0;
        __syncthreads();
        s[t] += u;
        __syncthreads();
    }
    if (t == SCAN_T - 1)
        ((volatile int*)g_bsum)[b] = s[SCAN_T - 1];
    if (t < b) {
        int val;
        do { val = ((volatile int*)g_bsum)[t]; } while (val < 0);
        atomicAdd(&s_boff, val);
    }
    __syncthreads();
    if (i < N_NODES) {
        int off = s[t] - v + s_boff;
        g_off[i] = off;
        g_cur[i] = off;
    }
}

// ---------------- CSR scatter: src only (weights factored into rows) --------
__global__ void k_scatter(const void* ep) {
    int e = blockIdx.x * blockDim.x + threadIdx.x;
    if (e >= N_EDGES) return;
    int s = load_idx(ep, e);
    int d = load_idx(ep, (long long)N_EDGES + e);
    int pos = atomicAdd(&g_cur[d], 1);
    g_csr[pos] = s;
}

// ---------------- GEMM: Y16 = X16 @ W (fp16 MMA, cp.async pipeline) ---------
// SCALE: multiply output row r by g_dinv[r] (layer-1 pre-scaling).
#define KS 136
#define SUBT 4
#define ABUF (64 * KS)
#define GEMM_SMEM ((2 * ABUF + 128 * KS) * 2)  // 69632 B -> 3 CTAs/SM

template <bool SCALE>
__global__ void __launch_bounds__(256, 3) k_gemm(const uint2* __restrict__ X16,
                                                 const uint32_t* __restrict__ Wp,
                                                 __half* __restrict__ Y16,
                                                 int tileOff) {
    extern __shared__ __half sm[];
    __half* sA = sm;
    __half* sW = sA + 2 * ABUF;

    const int tid = threadIdx.x;
    const int rowBase0 = (tileOff + blockIdx.x) * (64 * SUBT);
    const uint32_t sA0 = sptr(sA);
    const char* Xb = (const char*)X16;

    int gtid = blockIdx.x * 256 + tid;
    if (gtid < N_GRAPHS * D) g_pool[gtid] = 0.0f;
    if (gtid < N_GRAPHS) g_cnt[gtid] = 0;

    int sr[4], sc[4];
    #pragma unroll
    for (int j = 0; j < 4; j++) {
        int i = tid + j * 256;
        sr[j] = i >> 4;
        sc[j] = i & 15;
    }

    #pragma unroll
    for (int j = 0; j < 4; j++) {
        int row = rowBase0 + sr[j];
        cp_async16(sA0 + sr[j] * (KS * 2) + sc[j] * 16,
                   Xb + (size_t)row * 256 + sc[j] * 16,
                   row < N_NODES ? 16u : 0u);
    }
    cp_commit();

    const uint4* Wp4 = (const uint4*)Wp;
    uint32_t* sW32 = (uint32_t*)sW;
    #pragma unroll
    for (int i = tid; i < 128 * 16; i += 256) {
        int n = i >> 4, kq = i & 15;
        *(uint4*)&sW32[n * (KS / 2) + kq * 4] = Wp4[i];
    }

    const int wid = tid >> 5, lane = tid & 31;
    const int g = lane >> 2, tg = lane & 3;
    const int mbase = (wid >> 2) * 32;
    const int nbase = (wid & 3) * 32;

    const int jj = lane >> 3, rr = lane & 7;
    uint32_t aBase[2];
    #pragma unroll
    for (int mf = 0; mf < 2; mf++) {
        int row = mbase + mf * 16 + ((jj & 1) * 8) + rr;
        int col = (jj >> 1) * 8;
        aBase[mf] = sptr(&sA[row * KS + col]);
    }
    uint32_t bBase[2];
    #pragma unroll
    for (int p = 0; p < 2; p++) {
        int row = nbase + p * 16 + ((jj >> 1) * 8) + rr;
        int col = (jj & 1) * 8;
        bBase[p] = sptr(&sW[row * KS + col]);
    }

    for (int st = 0; st < SUBT; st++) {
        const int rowBase = rowBase0 + st * 64;
        const uint32_t abytes = (uint32_t)((st & 1) * ABUF * 2);

        if (st + 1 < SUBT) {
            uint32_t dstb = sA0 + ((st + 1) & 1) * (ABUF * 2);
            #pragma unroll
            for (int j = 0; j < 4; j++) {
                int row = rowBase + 64 + sr[j];
                cp_async16(dstb + sr[j] * (KS * 2) + sc[j] * 16,
                           Xb + (size_t)row * 256 + sc[j] * 16,
                           row < N_NODES ? 16u : 0u);
            }
            cp_commit();
            cp_wait<1>();
        } else {
            cp_wait<0>();
        }
        __syncthreads();

        float acc[2][4][4];
        #pragma unroll
        for (int mf = 0; mf < 2; mf++)
            #pragma unroll
            for (int nf = 0; nf < 4; nf++)
                #pragma unroll
                for (int j = 0; j < 4; j++) acc[mf][nf][j] = 0.f;

        #pragma unroll
        for (int kc = 0; kc < 8; kc++) {
            const uint32_t koff = kc * 32;
            uint32_t a[2][4];
            #pragma unroll
            for (int mf = 0; mf < 2; mf++)
                ldsm_x4(a[mf][0], a[mf][1], a[mf][2], a[mf][3],
                        aBase[mf] + abytes + koff);
            uint32_t b[4][2];
            #pragma unroll
            for (int p = 0; p < 2; p++)
                ldsm_x4(b[2 * p][0], b[2 * p][1], b[2 * p + 1][0],
                        b[2 * p + 1][1], bBase[p] + koff);
            #pragma unroll
            for (int mf = 0; mf < 2; mf++)
                #pragma unroll
                for (int nf = 0; nf < 4; nf++)
                    mma16f(acc[mf][nf], a[mf], b[nf]);
        }

        #pragma unroll
        for (int mf = 0; mf < 2; mf++) {
            int row = rowBase + mbase + mf * 16 + g;
            float d0 = 1.f, d1 = 1.f;
            if (SCALE) {
                if (row < N_NODES) d0 = g_dinv[row];
                if (row + 8 < N_NODES) d1 = g_dinv[row + 8];
            }
            #pragma unroll
            for (int nf = 0; nf < 4; nf++) {
                int col = nbase + nf * 8 + 2 * tg;
                if (row < N_NODES) {
                    __half2 h = __float22half2_rn(
                        make_float2(acc[mf][nf][0] * d0, acc[mf][nf][1] * d0));
                    *(__half2*)&Y16[(size_t)row * D + col] = h;
                }
                if (row + 8 < N_NODES) {
                    __half2 h = __float22half2_rn(
                        make_float2(acc[mf][nf][2] * d1, acc[mf][nf][3] * d1));
                    *(__half2*)&Y16[(size_t)(row + 8) * D + col] = h;
                }
            }
        }
        __syncthreads();
    }
}

// ---------------- agg1: h1' = dinv * relu(dinv*sum + b1), fp16 --------------
__global__ void k_agg(const __half* __restrict__ hin,
                      __half* __restrict__ hout,
                      const float* __restrict__ bias,
                      int nodeBase, int nNodes) {
    int li = (blockIdx.x * blockDim.x + threadIdx.x) >> 5;
    if (li >= nNodes) return;
    int node = nodeBase + li;
    if (node >= N_NODES) return;
    int lane = threadIdx.x & 31;

    const uint2* hp = (const uint2*)hin;
    const float4 b = ((const float4*)bias)[lane];
    float4 s = gather_sum16(hp, node, lane);
    float dii = g_dinv[node];
    float4 r;
    r.x = fmaxf(fmaf(s.x, dii, b.x), 0.f) * dii;
    r.y = fmaxf(fmaf(s.y, dii, b.y), 0.f) * dii;
    r.z = fmaxf(fmaf(s.z, dii, b.z), 0.f) * dii;
    r.w = fmaxf(fmaf(s.w, dii, b.w), 0.f) * dii;
    ((uint2*)hout)[(size_t)node * 32 + lane] = f4toh4(r);
}

// ---------------- FUSED B: h2 = relu(dinv*sum + b2); pool -------------------
#define HS 132
__global__ void __launch_bounds__(256) k_fused_ap(const __half* __restrict__ T2,
                                                  const float* __restrict__ bias,
                                                  const void* batchp) {
    __shared__ float sH[64 * HS];
    __shared__ int sg[64];

    const int tid = threadIdx.x;
    const int wid = tid >> 5, lane = tid & 31;
    const int rowBase = blockIdx.x * 64;
    const int n_here = min(64, N_NODES - rowBase);

    if (tid < 64 && rowBase + tid < N_NODES) {
        sg[tid] = load_idx(batchp, rowBase + tid);
        g_deg[rowBase + tid] = 0;            // prep next replay
    }

    const uint2* hp = (const uint2*)T2;
    const float4 bvec = ((const float4*)bias)[lane];
    #pragma unroll
    for (int i = 0; i < 8; i++) {
        int r = wid * 8 + i;
        int node = rowBase + r;
        if (node < N_NODES) {
            float4 s = gather_sum16(hp, node, lane);
            float dii = g_dinv[node];
            float4 v;
            v.x = fmaxf(fmaf(s.x, dii, bvec.x), 0.f);
            v.y = fmaxf(fmaf(s.y, dii, bvec.y), 0.f);
            v.z = fmaxf(fmaf(s.z, dii, bvec.z), 0.f);
            v.w = fmaxf(fmaf(s.w, dii, bvec.w), 0.f);
            *(float4*)&sH[r * HS + lane * 4] = v;
        }
    }
    __syncthreads();

    if (tid < 128) {
        float acc = 0.f;
        int cur = sg[0];
        int runstart = 0;
        for (int n = 0; n < n_here; n++) {
            int g = sg[n];
            if (g != cur) {
                atomicAdd(&g_pool[cur * D + tid], acc);
                if (tid == 0) atomicAdd(&g_cnt[cur], n - runstart);
                acc = 0.f; cur = g; runstart = n;
            }
            acc += sH[n * HS + tid];
        }
        atomicAdd(&g_pool[cur * D + tid], acc);
        if (tid == 0) atomicAdd(&g_cnt[cur], n_here - runstart);
    }
}

// ---------------- final FC ---------------------------------------------------
__global__ void k_fc(const float* __restrict__ Wfc,
                     const float* __restrict__ bfc,
                     float* __restrict__ out) {
    __shared__ float srow[D];
    int g = blockIdx.x;
    int t = threadIdx.x;
    float cnt = fmaxf((float)g_cnt[g], 1.0f);
    srow[t] = g_pool[g * D + t] / cnt;
    __syncthreads();
    float acc = bfc[t];
    #pragma unroll 4
    for (int k = 0; k < D; k++)
        acc = fmaf(srow[k], Wfc[k * D + t], acc);
    out[g * D + t] = fmaxf(acc, 0.f);
}

// ---------------- launch ----------------------------------------------------
extern "C" void kernel_launch(void* const* d_in, const int* in_sizes, int n_in,
                              void* d_out, int out_size) {
    const float* x    = (const float*)d_in[0];
    const void*  edge = d_in[1];
    const void*  batch= d_in[2];
    const float* W1   = (const float*)d_in[3];
    const float* b1   = (const float*)d_in[4];
    const float* W2   = (const float*)d_in[5];
    const float* b2   = (const float*)d_in[6];
    const float* Wfc  = (const float*)d_in[7];
    const float* bfc  = (const float*)d_in[8];
    float* out = (float*)d_out;

    void *px16, *pt1, *pt2, *ph1, *pw;
    cudaGetSymbolAddress(&px16, g_x16);
    cudaGetSymbolAddress(&pt1, g_t1);
    cudaGetSymbolAddress(&pt2, g_t2);
    cudaGetSymbolAddress(&ph1, g_h1);
    cudaGetSymbolAddress(&pw, g_W16);
    uint2* x16 = (uint2*)px16;
    __half* t1 = (__half*)pt1;
    __half* t2 = (__half*)pt2;
    __half* h1 = (__half*)ph1;
    uint32_t* wp = (uint32_t*)pw;

    cudaFuncSetAttribute(k_gemm<true>,
                         cudaFuncAttributeMaxDynamicSharedMemorySize, GEMM_SMEM);
    cudaFuncSetAttribute(k_gemm<false>,
                         cudaFuncAttributeMaxDynamicSharedMemorySize, GEMM_SMEM);

    const int EB = (N_EDGES + 255) / 256;
    const int TILE_GRID = (N_NODES + 63) / 64;                      // 1563
    const int NODES_C0 = ROWS_C0;                // 50176
    const int NODES_C1 = N_NODES - ROWS_C0;      // 49824
    const int AGG_B0 = (NODES_C0 * 32 + 255) / 256;
    const int AGG_B1 = (NODES_C1 * 32 + 255) / 256;

    cudaStream_t s1 = nullptr;
    cudaEvent_t evFork = nullptr, evScan = nullptr, evG1 = nullptr;
    cudaEvent_t evA0 = nullptr, evA1 = nullptr, evG2 = nullptr;
    bool forked =
        cudaStreamCreateWithFlags(&s1, cudaStreamNonBlocking) == cudaSuccess &&
        cudaEventCreateWithFlags(&evFork, cudaEventDisableTiming) == cudaSuccess &&
        cudaEventCreateWithFlags(&evScan, cudaEventDisableTiming) == cudaSuccess &&
        cudaEventCreateWithFlags(&evG1, cudaEventDisableTiming) == cudaSuccess &&
        cudaEventCreateWithFlags(&evA0, cudaEventDisableTiming) == cudaSuccess &&
        cudaEventCreateWithFlags(&evA1, cudaEventDisableTiming) == cudaSuccess &&
        cudaEventCreateWithFlags(&evG2, cudaEventDisableTiming) == cudaSuccess;

    if (forked) {
        // fork: side stream does conversions immediately
        cudaEventRecord(evFork, 0);
        cudaStreamWaitEvent(s1, evFork, 0);
        k_conv<<<EB, 256, 0, s1>>>(x, W1, W2);

        // main: graph topology
        k_deg<<<EB, 256>>>(edge);
        k_scan<<<NB, SCAN_T>>>();
        cudaEventRecord(evScan, 0);

        // side: gemm1 (needs conv + dinv), overlaps scatter
        cudaStreamWaitEvent(s1, evScan, 0);
        k_gemm<true><<<TILES_TOTAL, 256, GEMM_SMEM, s1>>>(x16, wp, t1, 0);
        cudaEventRecord(evG1, s1);

        // main: scatter
        k_scatter<<<EB, 256>>>(edge);

        // join for agg1; chunked agg1 <-> gemm2 pipeline
        cudaStreamWaitEvent(0, evG1, 0);
        k_agg<<<AGG_B0, 256>>>(t1, h1, b1, 0, NODES_C0);
        cudaEventRecord(evA0, 0);
        cudaStreamWaitEvent(s1, evA0, 0);
        k_gemm<false><<<TILES_C0, 256, GEMM_SMEM, s1>>>(
            (const uint2*)h1, wp + D * 64, t2, 0);
        k_agg<<<AGG_B1, 256>>>(t1, h1, b1, NODES_C0, NODES_C1);
        cudaEventRecord(evA1, 0);
        cudaStreamWaitEvent(s1, evA1, 0);
        k_gemm<false><<<TILES_TOTAL - TILES_C0, 256, GEMM_SMEM, s1>>>(
            (const uint2*)h1, wp + D * 64, t2, TILES_C0);
        cudaEventRecord(evG2, s1);
        cudaStreamWaitEvent(0, evG2, 0);
    } else {
        // sequential fallback
        k_conv<<<EB, 256>>>(x, W1, W2);
        k_deg<<<EB, 256>>>(edge);
        k_scan<<<NB, SCAN_T>>>();
        k_scatter<<<EB, 256>>>(edge);
        k_gemm<true><<<TILES_TOTAL, 256, GEMM_SMEM>>>(x16, wp, t1, 0);
        k_agg<<<(N_NODES * 32 + 255) / 256, 256>>>(t1, h1, b1, 0, N_NODES);
        k_gemm<false><<<TILES_TOTAL, 256, GEMM_SMEM>>>(
            (const uint2*)h1, wp + D * 64, t2, 0);
    }

    k_fused_ap<<<TILE_GRID, 256>>>(t2, b2, batch);
    k_fc<<<N_GRAPHS, D>>>(Wfc, bfc, out);
}

// round 16
// speedup vs baseline: 1.0930x; 1.0930x over previous
#include <cuda_runtime.h>
#include <cuda_bf16.h>
#include <cuda_fp16.h>
#include <cstdint>

#define N_NODES 100000
#define N_EDGES 1600000
#define N_GRAPHS 64
#define D 128

#define SCAN_T 1024
#define NB ((N_NODES + SCAN_T - 1) / SCAN_T)   // 98

// ---------------- scratch (device globals; no allocation allowed) ----------
__device__ uint2  g_x16[(size_t)N_NODES * 32]; // X in fp16 (packed 4/uint2)
__device__ __half g_t1[(size_t)N_NODES * D];  // X@W1, fp16 (unscaled)
__device__ __half g_h1[(size_t)N_NODES * D];  // relu(...), fp16 (unscaled)
__device__ __half g_t2[(size_t)N_NODES * D];  // h1@W2, fp16 (unscaled)
__device__ int   g_deg[N_NODES];              // zeroed by k_fused_ap for next call
__device__ float g_dinv[N_NODES];
__device__ int   g_off[N_NODES + 1];
__device__ int   g_cur[N_NODES];
__device__ int   g_csr[N_EDGES];              // src only
__device__ int   g_bsum[NB];                  // re-armed to -1 by k_deg
__device__ float g_pool[N_GRAPHS * D];        // zeroed by k_conv
__device__ int   g_cnt[N_GRAPHS];
__device__ int   g_is64;
__device__ uint32_t g_W16[2][D * 64];         // W^T fp16, packed pairs [n][k/2]

// ---------------- helpers ---------------------------------------------------
__device__ __forceinline__ int load_idx(const void* p, long long i) {
    if (g_is64) return (int)((const long long*)p)[i];
    return ((const int*)p)[i];
}

__device__ __forceinline__ int detect64(const void* ep) {
    const int* p = (const int*)ep;
    int is64 = 1;
    #pragma unroll
    for (int j = 0; j < 8; j++)
        if (p[2 * j + 1] != 0) is64 = 0;
    return is64;
}

__device__ __forceinline__ void mma16f(float* c, const uint32_t* a,
                                       const uint32_t* b) {
    asm volatile(
        "mma.sync.aligned.m16n8k16.row.col.f32.f16.f16.f32 "
        "{%0,%1,%2,%3}, {%4,%5,%6,%7}, {%8,%9}, {%0,%1,%2,%3};"
        : "+f"(c[0]), "+f"(c[1]), "+f"(c[2]), "+f"(c[3])
        : "r"(a[0]), "r"(a[1]), "r"(a[2]), "r"(a[3]), "r"(b[0]), "r"(b[1]));
}

__device__ __forceinline__ void ldsm_x4(uint32_t& r0, uint32_t& r1,
                                        uint32_t& r2, uint32_t& r3,
                                        uint32_t addr) {
    asm volatile(
        "ldmatrix.sync.aligned.m8n8.x4.shared.b16 {%0,%1,%2,%3}, [%4];"
        : "=r"(r0), "=r"(r1), "=r"(r2), "=r"(r3) : "r"(addr));
}

__device__ __forceinline__ uint32_t sptr(const void* p) {
    return (uint32_t)__cvta_generic_to_shared(p);
}

__device__ __forceinline__ void cp_async16(uint32_t dst, const void* src,
                                           uint32_t srcsize) {
    asm volatile("cp.async.ca.shared.global [%0], [%1], 16, %2;"
                 :: "r"(dst), "l"(src), "r"(srcsize) : "memory");
}
__device__ __forceinline__ void cp_commit() {
    asm volatile("cp.async.commit_group;" ::: "memory");
}
template <int N>
__device__ __forceinline__ void cp_wait() {
    asm volatile("cp.async.wait_group %0;" :: "n"(N) : "memory");
}

__device__ __forceinline__ float4 h4tof4(uint2 v) {
    float2 a = __half22float2(*reinterpret_cast<__half2*>(&v.x));
    float2 b = __half22float2(*reinterpret_cast<__half2*>(&v.y));
    return make_float4(a.x, a.y, b.x, b.y);
}

__device__ __forceinline__ uint2 f4toh4(float4 v) {
    __half2 a = __float22half2_rn(make_float2(v.x, v.y));
    __half2 b = __float22half2_rn(make_float2(v.z, v.w));
    uint2 o;
    o.x = *reinterpret_cast<uint32_t*>(&a);
    o.y = *reinterpret_cast<uint32_t*>(&b);
    return o;
}

// weighted gather: dinv[node]*row[node] + sum_e dinv[src]*row[src]
// (dinv table is 400KB -> L1/L2 resident; per-edge extra load is cheap)
__device__ __forceinline__ float4 gather_w16(const uint2* __restrict__ hp,
                                             int node, int lane) {
    float dii = g_dinv[node];
    float4 s0 = h4tof4(hp[(size_t)node * 32 + lane]);
    float4 acc[4];
    acc[0] = make_float4(s0.x * dii, s0.y * dii, s0.z * dii, s0.w * dii);
    acc[1] = make_float4(0.f, 0.f, 0.f, 0.f);
    acc[2] = acc[1];
    acc[3] = acc[1];

    int e = g_off[node];
    const int end = g_off[node + 1];
    for (; e + 3 < end; e += 4) {
        int s[4];
        #pragma unroll
        for (int j = 0; j < 4; j++) s[j] = g_csr[e + j];
        uint2 raw[4];
        #pragma unroll
        for (int j = 0; j < 4; j++) raw[j] = hp[(size_t)s[j] * 32 + lane];
        float w[4];
        #pragma unroll
        for (int j = 0; j < 4; j++) w[j] = g_dinv[s[j]];
        #pragma unroll
        for (int j = 0; j < 4; j++) {
            float4 v = h4tof4(raw[j]);
            acc[j].x = fmaf(v.x, w[j], acc[j].x);
            acc[j].y = fmaf(v.y, w[j], acc[j].y);
            acc[j].z = fmaf(v.z, w[j], acc[j].z);
            acc[j].w = fmaf(v.w, w[j], acc[j].w);
        }
    }
    for (; e < end; e++) {
        int s = g_csr[e];
        float w = g_dinv[s];
        float4 v = h4tof4(hp[(size_t)s * 32 + lane]);
        acc[0].x = fmaf(v.x, w, acc[0].x);
        acc[0].y = fmaf(v.y, w, acc[0].y);
        acc[0].z = fmaf(v.z, w, acc[0].z);
        acc[0].w = fmaf(v.w, w, acc[0].w);
    }
    return make_float4(acc[0].x + acc[1].x + acc[2].x + acc[3].x,
                       acc[0].y + acc[1].y + acc[2].y + acc[3].y,
                       acc[0].z + acc[1].z + acc[2].z + acc[3].z,
                       acc[0].w + acc[1].w + acc[2].w + acc[3].w);
}

// ---------------- branch B: convert W + X to fp16; zero pool ----------------
__global__ void k_conv(const float* X, const float* W1, const float* W2) {
    int i = blockIdx.x * blockDim.x + threadIdx.x;
    if (i < N_GRAPHS * D) g_pool[i] = 0.0f;
    if (i < N_GRAPHS) g_cnt[i] = 0;
    if (i < 2 * D * 64) {
        int m = i >> 13;
        int j = i & 8191;
        int n = j >> 6, kp = j & 63;
        const float* W = m ? W2 : W1;
        float a = W[(2 * kp) * D + n];
        float b = W[(2 * kp + 1) * D + n];
        __half2 h = __float22half2_rn(make_float2(a, b));
        g_W16[m][n * 64 + kp] = *reinterpret_cast<uint32_t*>(&h);
    }
    #pragma unroll
    for (int j = 0; j < 2; j++) {
        int idx = i + j * (N_NODES * 16);
        if (idx < N_NODES * 32)
            g_x16[idx] = f4toh4(((const float4*)X)[idx]);
    }
}

// ---------------- branch A: deg count + dtype + sentinels --------------------
__global__ void k_deg(const void* ep) {
    int i = blockIdx.x * blockDim.x + threadIdx.x;
    if (i == 0) {
        g_is64 = detect64(ep);
        g_off[N_NODES] = N_EDGES;
    }
    if (i < NB) g_bsum[i] = -1;
    if (i < N_EDGES) {
        int is64 = detect64(ep);
        int d = is64 ? (int)((const long long*)ep)[(long long)N_EDGES + i]
                     : ((const int*)ep)[N_EDGES + i];
        atomicAdd(&g_deg[d], 1);
    }
}

// ---------------- single-pass scan (98 blocks = 1 wave; spin publication) ---
__global__ void k_scan() {
    __shared__ int s[SCAN_T];
    __shared__ int s_boff;
    const int b = blockIdx.x;
    const int t = threadIdx.x;
    const int i = b * SCAN_T + t;
    int v = (i < N_NODES) ? g_deg[i] : 0;
    if (i < N_NODES) g_dinv[i] = rsqrtf((float)v + 1.0f);  // +1 self loop
    s[t] = v;
    if (t == 0) s_boff = 0;
    __syncthreads();
    #pragma unroll
    for (int off = 1; off < SCAN_T; off <<= 1) {
        int u = (t >= off) ? s[t - off] : 0;
        __syncthreads();
        s[t] += u;
        __syncthreads();
    }
    if (t == SCAN_T - 1)
        ((volatile int*)g_bsum)[b] = s[SCAN_T - 1];
    if (t < b) {
        int val;
        do { val = ((volatile int*)g_bsum)[t]; } while (val < 0);
        atomicAdd(&s_boff, val);
    }
    __syncthreads();
    if (i < N_NODES) {
        int off = s[t] - v + s_boff;
        g_off[i] = off;
        g_cur[i] = off;
    }
}

// ---------------- CSR scatter: src only --------------------------------------
__global__ void k_scatter(const void* ep) {
    int e = blockIdx.x * blockDim.x + threadIdx.x;
    if (e >= N_EDGES) return;
    int s = load_idx(ep, e);
    int d = load_idx(ep, (long long)N_EDGES + e);
    int pos = atomicAdd(&g_cur[d], 1);
    g_csr[pos] = s;
}

// ---------------- GEMM: Y16 = X16 @ W (fp16 MMA, cp.async pipeline) ---------
#define KS 136
#define SUBT 4
#define ABUF (64 * KS)
#define GEMM_SMEM ((2 * ABUF + 128 * KS) * 2)  // 69632 B -> 3 CTAs/SM

__global__ void __launch_bounds__(256, 3) k_gemm(const uint2* __restrict__ X16,
                                                 const uint32_t* __restrict__ Wp,
                                                 __half* __restrict__ Y16) {
    extern __shared__ __half sm[];
    __half* sA = sm;
    __half* sW = sA + 2 * ABUF;

    const int tid = threadIdx.x;
    const int rowBase0 = blockIdx.x * (64 * SUBT);
    const uint32_t sA0 = sptr(sA);
    const char* Xb = (const char*)X16;

    int sr[4], sc[4];
    #pragma unroll
    for (int j = 0; j < 4; j++) {
        int i = tid + j * 256;
        sr[j] = i >> 4;
        sc[j] = i & 15;
    }

    #pragma unroll
    for (int j = 0; j < 4; j++) {
        int row = rowBase0 + sr[j];
        cp_async16(sA0 + sr[j] * (KS * 2) + sc[j] * 16,
                   Xb + (size_t)row * 256 + sc[j] * 16,
                   row < N_NODES ? 16u : 0u);
    }
    cp_commit();

    const uint4* Wp4 = (const uint4*)Wp;
    uint32_t* sW32 = (uint32_t*)sW;
    #pragma unroll
    for (int i = tid; i < 128 * 16; i += 256) {
        int n = i >> 4, kq = i & 15;
        *(uint4*)&sW32[n * (KS / 2) + kq * 4] = Wp4[i];
    }

    const int wid = tid >> 5, lane = tid & 31;
    const int g = lane >> 2, tg = lane & 3;
    const int mbase = (wid >> 2) * 32;
    const int nbase = (wid & 3) * 32;

    const int jj = lane >> 3, rr = lane & 7;
    uint32_t aBase[2];
    #pragma unroll
    for (int mf = 0; mf < 2; mf++) {
        int row = mbase + mf * 16 + ((jj & 1) * 8) + rr;
        int col = (jj >> 1) * 8;
        aBase[mf] = sptr(&sA[row * KS + col]);
    }
    uint32_t bBase[2];
    #pragma unroll
    for (int p = 0; p < 2; p++) {
        int row = nbase + p * 16 + ((jj >> 1) * 8) + rr;
        int col = (jj & 1) * 8;
        bBase[p] = sptr(&sW[row * KS + col]);
    }

    for (int st = 0; st < SUBT; st++) {
        const int rowBase = rowBase0 + st * 64;
        const uint32_t abytes = (uint32_t)((st & 1) * ABUF * 2);

        if (st + 1 < SUBT) {
            uint32_t dstb = sA0 + ((st + 1) & 1) * (ABUF * 2);
            #pragma unroll
            for (int j = 0; j < 4; j++) {
                int row = rowBase + 64 + sr[j];
                cp_async16(dstb + sr[j] * (KS * 2) + sc[j] * 16,
                           Xb + (size_t)row * 256 + sc[j] * 16,
                           row < N_NODES ? 16u : 0u);
            }
            cp_commit();
            cp_wait<1>();
        } else {
            cp_wait<0>();
        }
        __syncthreads();

        float acc[2][4][4];
        #pragma unroll
        for (int mf = 0; mf < 2; mf++)
            #pragma unroll
            for (int nf = 0; nf < 4; nf++)
                #pragma unroll
                for (int j = 0; j < 4; j++) acc[mf][nf][j] = 0.f;

        #pragma unroll
        for (int kc = 0; kc < 8; kc++) {
            const uint32_t koff = kc * 32;
            uint32_t a[2][4];
            #pragma unroll
            for (int mf = 0; mf < 2; mf++)
                ldsm_x4(a[mf][0], a[mf][1], a[mf][2], a[mf][3],
                        aBase[mf] + abytes + koff);
            uint32_t b[4][2];
            #pragma unroll
            for (int p = 0; p < 2; p++)
                ldsm_x4(b[2 * p][0], b[2 * p][1], b[2 * p + 1][0],
                        b[2 * p + 1][1], bBase[p] + koff);
            #pragma unroll
            for (int mf = 0; mf < 2; mf++)
                #pragma unroll
                for (int nf = 0; nf < 4; nf++)
                    mma16f(acc[mf][nf], a[mf], b[nf]);
        }

        #pragma unroll
        for (int mf = 0; mf < 2; mf++) {
            int row = rowBase + mbase + mf * 16 + g;
            #pragma unroll
            for (int nf = 0; nf < 4; nf++) {
                int col = nbase + nf * 8 + 2 * tg;
                if (row < N_NODES) {
                    __half2 h = __float22half2_rn(
                        make_float2(acc[mf][nf][0], acc[mf][nf][1]));
                    *(__half2*)&Y16[(size_t)row * D + col] = h;
                }
                if (row + 8 < N_NODES) {
                    __half2 h = __float22half2_rn(
                        make_float2(acc[mf][nf][2], acc[mf][nf][3]));
                    *(__half2*)&Y16[(size_t)(row + 8) * D + col] = h;
                }
            }
        }
        __syncthreads();
    }
}

// ---------------- agg1: h1 = relu(dinv*gatherW + b1), fp16 ------------------
__global__ void k_agg(const __half* __restrict__ hin,
                      __half* __restrict__ hout,
                      const float* __restrict__ bias) {
    int node = (blockIdx.x * blockDim.x + threadIdx.x) >> 5;
    if (node >= N_NODES) return;
    int lane = threadIdx.x & 31;

    const uint2* hp = (const uint2*)hin;
    const float4 b = ((const float4*)bias)[lane];
    float4 s = gather_w16(hp, node, lane);
    float dii = g_dinv[node];
    float4 r;
    r.x = fmaxf(fmaf(s.x, dii, b.x), 0.f);
    r.y = fmaxf(fmaf(s.y, dii, b.y), 0.f);
    r.z = fmaxf(fmaf(s.z, dii, b.z), 0.f);
    r.w = fmaxf(fmaf(s.w, dii, b.w), 0.f);
    ((uint2*)hout)[(size_t)node * 32 + lane] = f4toh4(r);
}

// ---------------- FUSED B: h2 = relu(dinv*gatherW + b2); pool ---------------
#define HS 132
__global__ void __launch_bounds__(256) k_fused_ap(const __half* __restrict__ T2,
                                                  const float* __restrict__ bias,
                                                  const void* batchp) {
    __shared__ float sH[64 * HS];
    __shared__ int sg[64];

    const int tid = threadIdx.x;
    const int wid = tid >> 5, lane = tid & 31;
    const int rowBase = blockIdx.x * 64;
    const int n_here = min(64, N_NODES - rowBase);

    if (tid < 64 && rowBase + tid < N_NODES) {
        sg[tid] = load_idx(batchp, rowBase + tid);
        g_deg[rowBase + tid] = 0;            // prep next replay
    }

    const uint2* hp = (const uint2*)T2;
    const float4 bvec = ((const float4*)bias)[lane];
    #pragma unroll
    for (int i = 0; i < 8; i++) {
        int r = wid * 8 + i;
        int node = rowBase + r;
        if (node < N_NODES) {
            float4 s = gather_w16(hp, node, lane);
            float dii = g_dinv[node];
            float4 v;
            v.x = fmaxf(fmaf(s.x, dii, bvec.x), 0.f);
            v.y = fmaxf(fmaf(s.y, dii, bvec.y), 0.f);
            v.z = fmaxf(fmaf(s.z, dii, bvec.z), 0.f);
            v.w = fmaxf(fmaf(s.w, dii, bvec.w), 0.f);
            *(float4*)&sH[r * HS + lane * 4] = v;
        }
    }
    __syncthreads();

    if (tid < 128) {
        float acc = 0.f;
        int cur = sg[0];
        int runstart = 0;
        for (int n = 0; n < n_here; n++) {
            int g = sg[n];
            if (g != cur) {
                atomicAdd(&g_pool[cur * D + tid], acc);
                if (tid == 0) atomicAdd(&g_cnt[cur], n - runstart);
                acc = 0.f; cur = g; runstart = n;
            }
            acc += sH[n * HS + tid];
        }
        atomicAdd(&g_pool[cur * D + tid], acc);
        if (tid == 0) atomicAdd(&g_cnt[cur], n_here - runstart);
    }
}

// ---------------- final FC ---------------------------------------------------
__global__ void k_fc(const float* __restrict__ Wfc,
                     const float* __restrict__ bfc,
                     float* __restrict__ out) {
    __shared__ float srow[D];
    int g = blockIdx.x;
    int t = threadIdx.x;
    float cnt = fmaxf((float)g_cnt[g], 1.0f);
    srow[t] = g_pool[g * D + t] / cnt;
    __syncthreads();
    float acc = bfc[t];
    #pragma unroll 4
    for (int k = 0; k < D; k++)
        acc = fmaf(srow[k], Wfc[k * D + t], acc);
    out[g * D + t] = fmaxf(acc, 0.f);
}

// ---------------- launch ----------------------------------------------------
extern "C" void kernel_launch(void* const* d_in, const int* in_sizes, int n_in,
                              void* d_out, int out_size) {
    const float* x    = (const float*)d_in[0];
    const void*  edge = d_in[1];
    const void*  batch= d_in[2];
    const float* W1   = (const float*)d_in[3];
    const float* b1   = (const float*)d_in[4];
    const float* W2   = (const float*)d_in[5];
    const float* b2   = (const float*)d_in[6];
    const float* Wfc  = (const float*)d_in[7];
    const float* bfc  = (const float*)d_in[8];
    float* out = (float*)d_out;

    void *px16, *pt1, *pt2, *ph1, *pw;
    cudaGetSymbolAddress(&px16, g_x16);
    cudaGetSymbolAddress(&pt1, g_t1);
    cudaGetSymbolAddress(&pt2, g_t2);
    cudaGetSymbolAddress(&ph1, g_h1);
    cudaGetSymbolAddress(&pw, g_W16);
    uint2* x16 = (uint2*)px16;
    __half* t1 = (__half*)pt1;
    __half* t2 = (__half*)pt2;
    __half* h1 = (__half*)ph1;
    uint32_t* wp = (uint32_t*)pw;

    cudaFuncSetAttribute(k_gemm,
                         cudaFuncAttributeMaxDynamicSharedMemorySize, GEMM_SMEM);

    const int EB = (N_EDGES + 255) / 256;
    const int GEMM_GRID = (N_NODES + 255) / 256;     // 391
    const int TILE_GRID = (N_NODES + 63) / 64;       // 1563
    const int AGG_BLOCKS = (N_NODES * 32 + 255) / 256;

    cudaStream_t s1 = nullptr;
    cudaEvent_t evFork = nullptr, evG1 = nullptr;
    bool forked =
        cudaStreamCreateWithFlags(&s1, cudaStreamNonBlocking) == cudaSuccess &&
        cudaEventCreateWithFlags(&evFork, cudaEventDisableTiming) == cudaSuccess &&
        cudaEventCreateWithFlags(&evG1, cudaEventDisableTiming) == cudaSuccess;

    if (forked) {
        // fork: side stream converts + runs gemm1 immediately (needs no
        // graph-topology data at all)
        cudaEventRecord(evFork, 0);
        cudaStreamWaitEvent(s1, evFork, 0);
        k_conv<<<EB, 256, 0, s1>>>(x, W1, W2);
        k_gemm<<<GEMM_GRID, 256, GEMM_SMEM, s1>>>(x16, wp, t1);
        cudaEventRecord(evG1, s1);

        // main: graph topology
        k_deg<<<EB, 256>>>(edge);
        k_scan<<<NB, SCAN_T>>>();
        k_scatter<<<EB, 256>>>(edge);

        // join
        cudaStreamWaitEvent(0, evG1, 0);
    } else {
        k_conv<<<EB, 256>>>(x, W1, W2);
        k_deg<<<EB, 256>>>(edge);
        k_scan<<<NB, SCAN_T>>>();
        k_scatter<<<EB, 256>>>(edge);
        k_gemm<<<GEMM_GRID, 256, GEMM_SMEM>>>(x16, wp, t1);
    }

    // layer 1 agg, layer 2 gemm, fused agg2+pool, fc
    k_agg<<<AGG_BLOCKS, 256>>>(t1, h1, b1);
    k_gemm<<<GEMM_GRID, 256, GEMM_SMEM>>>((const uint2*)h1, wp + D * 64, t2);
    k_fused_ap<<<TILE_GRID, 256>>>(t2, b2, batch);
    k_fc<<<N_GRAPHS, D>>>(Wfc, bfc, out);
}

// round 17
// speedup vs baseline: 1.0963x; 1.0030x over previous
#include <cuda_runtime.h>
#include <cuda_bf16.h>
#include <cuda_fp16.h>
#include <cstdint>

#define N_NODES 100000
#define N_EDGES 1600000
#define N_GRAPHS 64
#define D 128

#define SCAN_T 1024
#define NB ((N_NODES + SCAN_T - 1) / SCAN_T)   // 98

// chunk split for agg1 <-> gemm2 overlap (gemm tile = 256 rows)
#define TILES_TOTAL 391
#define TILES_C0 196
#define NODES_C0 (TILES_C0 * 256)   // 50176

// ---------------- scratch (device globals; no allocation allowed) ----------
__device__ uint2  g_x16[(size_t)N_NODES * 32]; // X in fp16 (packed 4/uint2)
__device__ __half g_t1[(size_t)N_NODES * D];  // X@W1, fp16 (unscaled)
__device__ __half g_h1[(size_t)N_NODES * D];  // relu(...), fp16 (unscaled)
__device__ __half g_t2[(size_t)N_NODES * D];  // h1@W2, fp16 (unscaled)
__device__ int   g_deg[N_NODES];              // zeroed by k_fused_ap for next call
__device__ float g_dinv[N_NODES];
__device__ int   g_off[N_NODES + 1];
__device__ int   g_cur[N_NODES];
__device__ int   g_csr[N_EDGES];              // src only
__device__ int   g_bsum[NB];                  // re-armed to -1 by k_deg
__device__ float g_pool[N_GRAPHS * D];        // zeroed by k_conv
__device__ int   g_cnt[N_GRAPHS];
__device__ int   g_is64;
__device__ uint32_t g_W16[2][D * 64];         // W^T fp16, packed pairs [n][k/2]

// ---------------- helpers ---------------------------------------------------
__device__ __forceinline__ int load_idx(const void* p, long long i) {
    if (g_is64) return (int)((const long long*)p)[i];
    return ((const int*)p)[i];
}

__device__ __forceinline__ int detect64(const void* ep) {
    const int* p = (const int*)ep;
    int is64 = 1;
    #pragma unroll
    for (int j = 0; j < 8; j++)
        if (p[2 * j + 1] != 0) is64 = 0;
    return is64;
}

__device__ __forceinline__ void mma16f(float* c, const uint32_t* a,
                                       const uint32_t* b) {
    asm volatile(
        "mma.sync.aligned.m16n8k16.row.col.f32.f16.f16.f32 "
        "{%0,%1,%2,%3}, {%4,%5,%6,%7}, {%8,%9}, {%0,%1,%2,%3};"
        : "+f"(c[0]), "+f"(c[1]), "+f"(c[2]), "+f"(c[3])
        : "r"(a[0]), "r"(a[1]), "r"(a[2]), "r"(a[3]), "r"(b[0]), "r"(b[1]));
}

__device__ __forceinline__ void ldsm_x4(uint32_t& r0, uint32_t& r1,
                                        uint32_t& r2, uint32_t& r3,
                                        uint32_t addr) {
    asm volatile(
        "ldmatrix.sync.aligned.m8n8.x4.shared.b16 {%0,%1,%2,%3}, [%4];"
        : "=r"(r0), "=r"(r1), "=r"(r2), "=r"(r3) : "r"(addr));
}

__device__ __forceinline__ uint32_t sptr(const void* p) {
    return (uint32_t)__cvta_generic_to_shared(p);
}

__device__ __forceinline__ void cp_async16(uint32_t dst, const void* src,
                                           uint32_t srcsize) {
    asm volatile("cp.async.ca.shared.global [%0], [%1], 16, %2;"
                 :: "r"(dst), "l"(src), "r"(srcsize) : "memory");
}
__device__ __forceinline__ void cp_commit() {
    asm volatile("cp.async.commit_group;" ::: "memory");
}
template <int N>
__device__ __forceinline__ void cp_wait() {
    asm volatile("cp.async.wait_group %0;" :: "n"(N) : "memory");
}

__device__ __forceinline__ float4 h4tof4(uint2 v) {
    float2 a = __half22float2(*reinterpret_cast<__half2*>(&v.x));
    float2 b = __half22float2(*reinterpret_cast<__half2*>(&v.y));
    return make_float4(a.x, a.y, b.x, b.y);
}

__device__ __forceinline__ uint2 f4toh4(float4 v) {
    __half2 a = __float22half2_rn(make_float2(v.x, v.y));
    __half2 b = __float22half2_rn(make_float2(v.z, v.w));
    uint2 o;
    o.x = *reinterpret_cast<uint32_t*>(&a);
    o.y = *reinterpret_cast<uint32_t*>(&b);
    return o;
}

// weighted gather: dinv[node]*row[node] + sum_e dinv[src]*row[src]
__device__ __forceinline__ float4 gather_w16(const uint2* __restrict__ hp,
                                             int node, int lane) {
    float dii = g_dinv[node];
    float4 s0 = h4tof4(hp[(size_t)node * 32 + lane]);
    float4 acc[4];
    acc[0] = make_float4(s0.x * dii, s0.y * dii, s0.z * dii, s0.w * dii);
    acc[1] = make_float4(0.f, 0.f, 0.f, 0.f);
    acc[2] = acc[1];
    acc[3] = acc[1];

    int e = g_off[node];
    const int end = g_off[node + 1];
    for (; e + 3 < end; e += 4) {
        int s[4];
        #pragma unroll
        for (int j = 0; j < 4; j++) s[j] = g_csr[e + j];
        uint2 raw[4];
        #pragma unroll
        for (int j = 0; j < 4; j++) raw[j] = hp[(size_t)s[j] * 32 + lane];
        float w[4];
        #pragma unroll
        for (int j = 0; j < 4; j++) w[j] = g_dinv[s[j]];
        #pragma unroll
        for (int j = 0; j < 4; j++) {
            float4 v = h4tof4(raw[j]);
            acc[j].x = fmaf(v.x, w[j], acc[j].x);
            acc[j].y = fmaf(v.y, w[j], acc[j].y);
            acc[j].z = fmaf(v.z, w[j], acc[j].z);
            acc[j].w = fmaf(v.w, w[j], acc[j].w);
        }
    }
    for (; e < end; e++) {
        int s = g_csr[e];
        float w = g_dinv[s];
        float4 v = h4tof4(hp[(size_t)s * 32 + lane]);
        acc[0].x = fmaf(v.x, w, acc[0].x);
        acc[0].y = fmaf(v.y, w, acc[0].y);
        acc[0].z = fmaf(v.z, w, acc[0].z);
        acc[0].w = fmaf(v.w, w, acc[0].w);
    }
    return make_float4(acc[0].x + acc[1].x + acc[2].x + acc[3].x,
                       acc[0].y + acc[1].y + acc[2].y + acc[3].y,
                       acc[0].z + acc[1].z + acc[2].z + acc[3].z,
                       acc[0].w + acc[1].w + acc[2].w + acc[3].w);
}

// ---------------- branch B: convert W + X to fp16; zero pool ----------------
__global__ void k_conv(const float* X, const float* W1, const float* W2) {
    int i = blockIdx.x * blockDim.x + threadIdx.x;
    if (i < N_GRAPHS * D) g_pool[i] = 0.0f;
    if (i < N_GRAPHS) g_cnt[i] = 0;
    if (i < 2 * D * 64) {
        int m = i >> 13;
        int j = i & 8191;
        int n = j >> 6, kp = j & 63;
        const float* W = m ? W2 : W1;
        float a = W[(2 * kp) * D + n];
        float b = W[(2 * kp + 1) * D + n];
        __half2 h = __float22half2_rn(make_float2(a, b));
        g_W16[m][n * 64 + kp] = *reinterpret_cast<uint32_t*>(&h);
    }
    #pragma unroll
    for (int j = 0; j < 2; j++) {
        int idx = i + j * (N_NODES * 16);
        if (idx < N_NODES * 32)
            g_x16[idx] = f4toh4(((const float4*)X)[idx]);
    }
}

// ---------------- branch A: deg count + dtype + sentinels --------------------
__global__ void k_deg(const void* ep) {
    int i = blockIdx.x * blockDim.x + threadIdx.x;
    if (i == 0) {
        g_is64 = detect64(ep);
        g_off[N_NODES] = N_EDGES;
    }
    if (i < NB) g_bsum[i] = -1;
    if (i < N_EDGES) {
        int is64 = detect64(ep);
        int d = is64 ? (int)((const long long*)ep)[(long long)N_EDGES + i]
                     : ((const int*)ep)[N_EDGES + i];
        atomicAdd(&g_deg[d], 1);
    }
}

// ---------------- warp-shuffle scan (98 blocks = 1 wave; spin publication) --
__global__ void k_scan() {
    __shared__ int wsum[32];
    __shared__ int s_boff;
    const int b = blockIdx.x;
    const int t = threadIdx.x;
    const int i = b * SCAN_T + t;
    const int lane = t & 31, warp = t >> 5;

    int v = (i < N_NODES) ? g_deg[i] : 0;
    if (i < N_NODES) g_dinv[i] = rsqrtf((float)v + 1.0f);  // +1 self loop

    // inclusive warp scan via shfl
    int x = v;
    #pragma unroll
    for (int o = 1; o < 32; o <<= 1) {
        int y = __shfl_up_sync(0xffffffff, x, o);
        if (lane >= o) x += y;
    }
    if (lane == 31) wsum[warp] = x;
    if (t == 0) s_boff = 0;
    __syncthreads();
    if (warp == 0) {
        int w = wsum[lane];
        #pragma unroll
        for (int o = 1; o < 32; o <<= 1) {
            int y = __shfl_up_sync(0xffffffff, w, o);
            if (lane >= o) w += y;
        }
        wsum[lane] = w;                    // inclusive warp-sum scan
    }
    __syncthreads();

    if (t == SCAN_T - 1)
        ((volatile int*)g_bsum)[b] = wsum[31];   // block total
    if (t < b) {
        int val;
        do { val = ((volatile int*)g_bsum)[t]; } while (val < 0);
        atomicAdd(&s_boff, val);
    }
    __syncthreads();
    if (i < N_NODES) {
        int exc = x - v + (warp ? wsum[warp - 1] : 0) + s_boff;
        g_off[i] = exc;
        g_cur[i] = exc;
    }
}

// ---------------- CSR scatter: src only --------------------------------------
__global__ void k_scatter(const void* ep) {
    int e = blockIdx.x * blockDim.x + threadIdx.x;
    if (e >= N_EDGES) return;
    int s = load_idx(ep, e);
    int d = load_idx(ep, (long long)N_EDGES + e);
    int pos = atomicAdd(&g_cur[d], 1);
    g_csr[pos] = s;
}

// ---------------- GEMM: Y16 = X16 @ W (fp16 MMA, cp.async pipeline) ---------
#define KS 136
#define SUBT 4
#define ABUF (64 * KS)
#define GEMM_SMEM ((2 * ABUF + 128 * KS) * 2)  // 69632 B -> 3 CTAs/SM

__global__ void __launch_bounds__(256, 3) k_gemm(const uint2* __restrict__ X16,
                                                 const uint32_t* __restrict__ Wp,
                                                 __half* __restrict__ Y16,
                                                 int tileOff) {
    extern __shared__ __half sm[];
    __half* sA = sm;
    __half* sW = sA + 2 * ABUF;

    const int tid = threadIdx.x;
    const int rowBase0 = (tileOff + blockIdx.x) * (64 * SUBT);
    const uint32_t sA0 = sptr(sA);
    const char* Xb = (const char*)X16;

    int sr[4], sc[4];
    #pragma unroll
    for (int j = 0; j < 4; j++) {
        int i = tid + j * 256;
        sr[j] = i >> 4;
        sc[j] = i & 15;
    }

    #pragma unroll
    for (int j = 0; j < 4; j++) {
        int row = rowBase0 + sr[j];
        cp_async16(sA0 + sr[j] * (KS * 2) + sc[j] * 16,
                   Xb + (size_t)row * 256 + sc[j] * 16,
                   row < N_NODES ? 16u : 0u);
    }
    cp_commit();

    const uint4* Wp4 = (const uint4*)Wp;
    uint32_t* sW32 = (uint32_t*)sW;
    #pragma unroll
    for (int i = tid; i < 128 * 16; i += 256) {
        int n = i >> 4, kq = i & 15;
        *(uint4*)&sW32[n * (KS / 2) + kq * 4] = Wp4[i];
    }

    const int wid = tid >> 5, lane = tid & 31;
    const int g = lane >> 2, tg = lane & 3;
    const int mbase = (wid >> 2) * 32;
    const int nbase = (wid & 3) * 32;

    const int jj = lane >> 3, rr = lane & 7;
    uint32_t aBase[2];
    #pragma unroll
    for (int mf = 0; mf < 2; mf++) {
        int row = mbase + mf * 16 + ((jj & 1) * 8) + rr;
        int col = (jj >> 1) * 8;
        aBase[mf] = sptr(&sA[row * KS + col]);
    }
    uint32_t bBase[2];
    #pragma unroll
    for (int p = 0; p < 2; p++) {
        int row = nbase + p * 16 + ((jj >> 1) * 8) + rr;
        int col = (jj & 1) * 8;
        bBase[p] = sptr(&sW[row * KS + col]);
    }

    for (int st = 0; st < SUBT; st++) {
        const int rowBase = rowBase0 + st * 64;
        const uint32_t abytes = (uint32_t)((st & 1) * ABUF * 2);

        if (st + 1 < SUBT) {
            uint32_t dstb = sA0 + ((st + 1) & 1) * (ABUF * 2);
            #pragma unroll
            for (int j = 0; j < 4; j++) {
                int row = rowBase + 64 + sr[j];
                cp_async16(dstb + sr[j] * (KS * 2) + sc[j] * 16,
                           Xb + (size_t)row * 256 + sc[j] * 16,
                           row < N_NODES ? 16u : 0u);
            }
            cp_commit();
            cp_wait<1>();
        } else {
            cp_wait<0>();
        }
        __syncthreads();

        float acc[2][4][4];
        #pragma unroll
        for (int mf = 0; mf < 2; mf++)
            #pragma unroll
            for (int nf = 0; nf < 4; nf++)
                #pragma unroll
                for (int j = 0; j < 4; j++) acc[mf][nf][j] = 0.f;

        #pragma unroll
        for (int kc = 0; kc < 8; kc++) {
            const uint32_t koff = kc * 32;
            uint32_t a[2][4];
            #pragma unroll
            for (int mf = 0; mf < 2; mf++)
                ldsm_x4(a[mf][0], a[mf][1], a[mf][2], a[mf][3],
                        aBase[mf] + abytes + koff);
            uint32_t b[4][2];
            #pragma unroll
            for (int p = 0; p < 2; p++)
                ldsm_x4(b[2 * p][0], b[2 * p][1], b[2 * p + 1][0],
                        b[2 * p + 1][1], bBase[p] + koff);
            #pragma unroll
            for (int mf = 0; mf < 2; mf++)
                #pragma unroll
                for (int nf = 0; nf < 4; nf++)
                    mma16f(acc[mf][nf], a[mf], b[nf]);
        }

        #pragma unroll
        for (int mf = 0; mf < 2; mf++) {
            int row = rowBase + mbase + mf * 16 + g;
            #pragma unroll
            for (int nf = 0; nf < 4; nf++) {
                int col = nbase + nf * 8 + 2 * tg;
                if (row < N_NODES) {
                    __half2 h = __float22half2_rn(
                        make_float2(acc[mf][nf][0], acc[mf][nf][1]));
                    *(__half2*)&Y16[(size_t)row * D + col] = h;
                }
                if (row + 8 < N_NODES) {
                    __half2 h = __float22half2_rn(
                        make_float2(acc[mf][nf][2], acc[mf][nf][3]));
                    *(__half2*)&Y16[(size_t)(row + 8) * D + col] = h;
                }
            }
        }
        __syncthreads();
    }
}

// ---------------- agg1: h1 = relu(dinv*gatherW + b1), fp16, chunked ---------
__global__ void k_agg(const __half* __restrict__ hin,
                      __half* __restrict__ hout,
                      const float* __restrict__ bias,
                      int nodeBase, int nNodes) {
    int li = (blockIdx.x * blockDim.x + threadIdx.x) >> 5;
    if (li >= nNodes) return;
    int node = nodeBase + li;
    if (node >= N_NODES) return;
    int lane = threadIdx.x & 31;

    const uint2* hp = (const uint2*)hin;
    const float4 b = ((const float4*)bias)[lane];
    float4 s = gather_w16(hp, node, lane);
    float dii = g_dinv[node];
    float4 r;
    r.x = fmaxf(fmaf(s.x, dii, b.x), 0.f);
    r.y = fmaxf(fmaf(s.y, dii, b.y), 0.f);
    r.z = fmaxf(fmaf(s.z, dii, b.z), 0.f);
    r.w = fmaxf(fmaf(s.w, dii, b.w), 0.f);
    ((uint2*)hout)[(size_t)node * 32 + lane] = f4toh4(r);
}

// ---------------- FUSED B: h2 = relu(dinv*gatherW + b2); pool ---------------
#define HS 132
__global__ void __launch_bounds__(256) k_fused_ap(const __half* __restrict__ T2,
                                                  const float* __restrict__ bias,
                                                  const void* batchp) {
    __shared__ float sH[64 * HS];
    __shared__ int sg[64];

    const int tid = threadIdx.x;
    const int wid = tid >> 5, lane = tid & 31;
    const int rowBase = blockIdx.x * 64;
    const int n_here = min(64, N_NODES - rowBase);

    if (tid < 64 && rowBase + tid < N_NODES) {
        sg[tid] = load_idx(batchp, rowBase + tid);
        g_deg[rowBase + tid] = 0;            // prep next replay
    }

    const uint2* hp = (const uint2*)T2;
    const float4 bvec = ((const float4*)bias)[lane];
    #pragma unroll
    for (int i = 0; i < 8; i++) {
        int r = wid * 8 + i;
        int node = rowBase + r;
        if (node < N_NODES) {
            float4 s = gather_w16(hp, node, lane);
            float dii = g_dinv[node];
            float4 v;
            v.x = fmaxf(fmaf(s.x, dii, bvec.x), 0.f);
            v.y = fmaxf(fmaf(s.y, dii, bvec.y), 0.f);
            v.z = fmaxf(fmaf(s.z, dii, bvec.z), 0.f);
            v.w = fmaxf(fmaf(s.w, dii, bvec.w), 0.f);
            *(float4*)&sH[r * HS + lane * 4] = v;
        }
    }
    __syncthreads();

    if (tid < 128) {
        float acc = 0.f;
        int cur = sg[0];
        int runstart = 0;
        for (int n = 0; n < n_here; n++) {
            int g = sg[n];
            if (g != cur) {
                atomicAdd(&g_pool[cur * D + tid], acc);
                if (tid == 0) atomicAdd(&g_cnt[cur], n - runstart);
                acc = 0.f; cur = g; runstart = n;
            }
            acc += sH[n * HS + tid];
        }
        atomicAdd(&g_pool[cur * D + tid], acc);
        if (tid == 0) atomicAdd(&g_cnt[cur], n_here - runstart);
    }
}

// ---------------- final FC ---------------------------------------------------
__global__ void k_fc(const float* __restrict__ Wfc,
                     const float* __restrict__ bfc,
                     float* __restrict__ out) {
    __shared__ float srow[D];
    int g = blockIdx.x;
    int t = threadIdx.x;
    float cnt = fmaxf((float)g_cnt[g], 1.0f);
    srow[t] = g_pool[g * D + t] / cnt;
    __syncthreads();
    float acc = bfc[t];
    #pragma unroll 4
    for (int k = 0; k < D; k++)
        acc = fmaf(srow[k], Wfc[k * D + t], acc);
    out[g * D + t] = fmaxf(acc, 0.f);
}

// ---------------- launch ----------------------------------------------------
extern "C" void kernel_launch(void* const* d_in, const int* in_sizes, int n_in,
                              void* d_out, int out_size) {
    const float* x    = (const float*)d_in[0];
    const void*  edge = d_in[1];
    const void*  batch= d_in[2];
    const float* W1   = (const float*)d_in[3];
    const float* b1   = (const float*)d_in[4];
    const float* W2   = (const float*)d_in[5];
    const float* b2   = (const float*)d_in[6];
    const float* Wfc  = (const float*)d_in[7];
    const float* bfc  = (const float*)d_in[8];
    float* out = (float*)d_out;

    void *px16, *pt1, *pt2, *ph1, *pw;
    cudaGetSymbolAddress(&px16, g_x16);
    cudaGetSymbolAddress(&pt1, g_t1);
    cudaGetSymbolAddress(&pt2, g_t2);
    cudaGetSymbolAddress(&ph1, g_h1);
    cudaGetSymbolAddress(&pw, g_W16);
    uint2* x16 = (uint2*)px16;
    __half* t1 = (__half*)pt1;
    __half* t2 = (__half*)pt2;
    __half* h1 = (__half*)ph1;
    uint32_t* wp = (uint32_t*)pw;

    cudaFuncSetAttribute(k_gemm,
                         cudaFuncAttributeMaxDynamicSharedMemorySize, GEMM_SMEM);

    const int EB = (N_EDGES + 255) / 256;
    const int TILE_GRID = (N_NODES + 63) / 64;       // 1563
    const int NODES_C1 = N_NODES - NODES_C0;         // 49824
    const int AGG_B0 = (NODES_C0 * 32 + 255) / 256;
    const int AGG_B1 = (NODES_C1 * 32 + 255) / 256;

    cudaStream_t s1 = nullptr;
    cudaEvent_t evFork = nullptr, evG1 = nullptr, evA0 = nullptr, evG2 = nullptr;
    bool forked =
        cudaStreamCreateWithFlags(&s1, cudaStreamNonBlocking) == cudaSuccess &&
        cudaEventCreateWithFlags(&evFork, cudaEventDisableTiming) == cudaSuccess &&
        cudaEventCreateWithFlags(&evG1, cudaEventDisableTiming) == cudaSuccess &&
        cudaEventCreateWithFlags(&evA0, cudaEventDisableTiming) == cudaSuccess &&
        cudaEventCreateWithFlags(&evG2, cudaEventDisableTiming) == cudaSuccess;

    if (forked) {
        // fork: side stream converts + runs gemm1 (no graph-topology deps)
        cudaEventRecord(evFork, 0);
        cudaStreamWaitEvent(s1, evFork, 0);
        k_conv<<<EB, 256, 0, s1>>>(x, W1, W2);
        k_gemm<<<TILES_TOTAL, 256, GEMM_SMEM, s1>>>(x16, wp, t1, 0);
        cudaEventRecord(evG1, s1);

        // main: graph topology
        k_deg<<<EB, 256>>>(edge);
        k_scan<<<NB, SCAN_T>>>();
        k_scatter<<<EB, 256>>>(edge);

        // join for agg1 chunk 0
        cudaStreamWaitEvent(0, evG1, 0);
        k_agg<<<AGG_B0, 256>>>(t1, h1, b1, 0, NODES_C0);
        cudaEventRecord(evA0, 0);

        // side: gemm2 chunk 0 overlaps agg1 chunk 1
        cudaStreamWaitEvent(s1, evA0, 0);
        k_gemm<<<TILES_C0, 256, GEMM_SMEM, s1>>>((const uint2*)h1,
                                                 wp + D * 64, t2, 0);
        cudaEventRecord(evG2, s1);

        // main: agg1 chunk 1, then gemm2 chunk 1
        k_agg<<<AGG_B1, 256>>>(t1, h1, b1, NODES_C0, NODES_C1);
        k_gemm<<<TILES_TOTAL - TILES_C0, 256, GEMM_SMEM>>>(
            (const uint2*)h1, wp + D * 64, t2, TILES_C0);

        // join gemm2 chunk 0 before fused_ap
        cudaStreamWaitEvent(0, evG2, 0);
    } else {
        k_conv<<<EB, 256>>>(x, W1, W2);
        k_deg<<<EB, 256>>>(edge);
        k_scan<<<NB, SCAN_T>>>();
        k_scatter<<<EB, 256>>>(edge);
        k_gemm<<<TILES_TOTAL, 256, GEMM_SMEM>>>(x16, wp, t1, 0);
        k_agg<<<(N_NODES * 32 + 255) / 256, 256>>>(t1, h1, b1, 0, N_NODES);
        k_gemm<<<TILES_TOTAL, 256, GEMM_SMEM>>>((const uint2*)h1,
                                                wp + D * 64, t2, 0);
    }

    k_fused_ap<<<TILE_GRID, 256>>>(t2, b2, batch);
    k_fc<<<N_GRAPHS, D>>>(Wfc, bfc, out);
}